// round 11
// baseline (speedup 1.0000x reference)
#include <cuda_runtime.h>
#include <cuda_fp16.h>
#include <cstdint>
#include <math.h>

#define HIDDEN    128
#define INPUT_SZ  64
#define NUM_ACT   16
#define BATCH_N   65536
#define TPB       512
#define BM        64
#define NTILES    (BATCH_N / BM)      // 1024
#define NCTA      148

// padded strides (in halfs) -> conflict-free ldmatrix
#define XSTR   72
#define W0STR  72
#define W1STR  136
#define WHSTR  136
#define HSTR   136
#define BUFSTR 17                      // head reduce buffer stride (floats)

// smem layout (bytes)
#define SM_X    0                      // 64*72*2    = 9216  (live every tile: prefetch target)
#define SM_W0   9216                   // 3*128*72*2 = 55296
#define SM_W1   64512                  // 3*128*136*2= 104448
#define SM_WH   168960                 // 32*136*2   = 8704
#define SM_H0   177664                 // 64*136*2   = 17408
#define SM_BUF  177664                 // [4][64][17] f32 = 17408 (aliases H0, dead at reduce)
#define SM_B0   195072                 // 384 f32
#define SM_B1   196608                 // 384 f32
#define SM_BP   198144                 // 16 f32
#define SM_BV   198208                 // 1 f32
#define SM_TOTAL 198272

// ---------------- precomputed fp16 tensors / f32 bias sums (device globals) --
__device__ __half gW0h[3 * 128 * 64];     // [g*128+j][64]
__device__ __half gW1h[3 * 128 * 128];    // [g*128+j][128]
__device__ __half gWHh[32 * 128];         // rows 0-15 Wp, 16 Wv, 17-31 zero
__device__ __half gXh[BATCH_N * INPUT_SZ];// x pre-converted to fp16
__device__ float  gB0[384], gB1[384], gBP[16], gBV[1];

__device__ __forceinline__ uint32_t smem_u32(const void* p) {
    uint32_t a;
    asm("{ .reg .u64 t; cvta.to.shared.u64 t, %1; cvt.u32.u64 %0, t; }"
        : "=r"(a) : "l"(p));
    return a;
}
__device__ __forceinline__ void cp16(uint32_t dst, const void* src) {
    asm volatile("cp.async.cg.shared.global [%0], [%1], 16;"
                 :: "r"(dst), "l"(src));
}
__device__ __forceinline__ void cp_commit() {
    asm volatile("cp.async.commit_group;" ::: "memory");
}
template <int N>
__device__ __forceinline__ void cp_wait() {
    asm volatile("cp.async.wait_group %0;" :: "n"(N) : "memory");
}
__device__ __forceinline__ void ldsm4(uint32_t& r0, uint32_t& r1, uint32_t& r2,
                                      uint32_t& r3, uint32_t addr) {
    asm volatile("ldmatrix.sync.aligned.m8n8.x4.shared.b16 {%0,%1,%2,%3}, [%4];"
                 : "=r"(r0), "=r"(r1), "=r"(r2), "=r"(r3) : "r"(addr));
}
__device__ __forceinline__ void ldsm2(uint32_t& r0, uint32_t& r1, uint32_t addr) {
    asm volatile("ldmatrix.sync.aligned.m8n8.x2.shared.b16 {%0,%1}, [%2];"
                 : "=r"(r0), "=r"(r1) : "r"(addr));
}
__device__ __forceinline__ void mma16816(float* d, const uint32_t* a,
                                         uint32_t b0, uint32_t b1) {
    asm volatile(
        "mma.sync.aligned.m16n8k16.row.col.f32.f16.f16.f32 "
        "{%0,%1,%2,%3}, {%4,%5,%6,%7}, {%8,%9}, {%0,%1,%2,%3};"
        : "+f"(d[0]), "+f"(d[1]), "+f"(d[2]), "+f"(d[3])
        : "r"(a[0]), "r"(a[1]), "r"(a[2]), "r"(a[3]), "r"(b0), "r"(b1));
}

// 6-MUFU hcell: sig(i)*tanh(g) = (2-B)/(A*B); h = (1-F)*rcp((1+F)*D)
__device__ __forceinline__ float hcell(float i, float g, float o) {
    i = fmaxf(i, -30.0f); g = fmaxf(g, -15.0f); o = fmaxf(o, -30.0f);
    float A = 1.0f + __expf(-i);
    float B = 1.0f + __expf(-2.0f * g);
    float c = (2.0f - B) * __fdividef(1.0f, A * B);   // sig(i)*tanh(g), in (-1,1)
    float F = __expf(-2.0f * c);
    float D = 1.0f + __expf(-o);
    return (1.0f - F) * __fdividef(1.0f, (1.0f + F) * D);
}
__device__ __forceinline__ int grow_of(int g) {   // live gates i,g,o in 4H blocks
    return (g == 0) ? 0 : (g == 1) ? 2 * HIDDEN : 3 * HIDDEN;
}
__device__ __forceinline__ uint32_t h2u(float a, float b) {
    __half2 h = __floats2half2_rn(a, b);
    return *reinterpret_cast<uint32_t*>(&h);
}

// =================== prep kernel: fp32 -> fp16 weights + x, bias sums ========
extern "C" __global__ void prep_weights(const float* __restrict__ x,
                                        const float* __restrict__ Wih0,
                                        const float* __restrict__ Wih1,
                                        const float* __restrict__ Wp,
                                        const float* __restrict__ Wv,
                                        const float* __restrict__ bih0,
                                        const float* __restrict__ bhh0,
                                        const float* __restrict__ bih1,
                                        const float* __restrict__ bhh1,
                                        const float* __restrict__ bp,
                                        const float* __restrict__ bv)
{
    const int tid = blockIdx.x * blockDim.x + threadIdx.x;
    const int nt  = gridDim.x * blockDim.x;
    const int NX8 = BATCH_N * INPUT_SZ / 8;
    for (int idx = tid; idx < NX8; idx += nt) {
        const float4* src = reinterpret_cast<const float4*>(x) + 2 * idx;
        float4 a = __ldg(src), b = __ldg(src + 1);
        uint4 u = make_uint4(h2u(a.x, a.y), h2u(a.z, a.w), h2u(b.x, b.y), h2u(b.z, b.w));
        *(reinterpret_cast<uint4*>(gXh) + idx) = u;
    }
    for (int idx = tid; idx < 3 * 128 * 64; idx += nt) {
        int rr = idx >> 6, c = idx & 63;
        int g = rr >> 7, j = rr & 127;
        gW0h[idx] = __float2half_rn(__ldg(Wih0 + (size_t)(grow_of(g) + j) * 64 + c));
    }
    for (int idx = tid; idx < 3 * 128 * 128; idx += nt) {
        int rr = idx >> 7, c = idx & 127;
        int g = rr >> 7, j = rr & 127;
        gW1h[idx] = __float2half_rn(__ldg(Wih1 + (size_t)(grow_of(g) + j) * 128 + c));
    }
    for (int idx = tid; idx < 32 * 128; idx += nt) {
        int row = idx >> 7, c = idx & 127;
        float v = (row < NUM_ACT) ? __ldg(Wp + row * 128 + c)
                : (row == NUM_ACT) ? __ldg(Wv + c) : 0.0f;
        gWHh[idx] = __float2half_rn(v);
    }
    for (int idx = tid; idx < 384; idx += nt) {
        int g = idx >> 7, j = idx & 127;
        int row = grow_of(g) + j;
        gB0[idx] = __ldg(bih0 + row) + __ldg(bhh0 + row);
        gB1[idx] = __ldg(bih1 + row) + __ldg(bhh1 + row);
    }
    if (tid < NUM_ACT) gBP[tid] = __ldg(bp + tid);
    if (tid == 0) gBV[0] = __ldg(bv);
}

// x tile -> smem via cp.async (512 16B chunks; 1 per thread)
__device__ __forceinline__ void stage_x(uint32_t sb, int tile, int tid) {
    const __half* src0 = gXh + (size_t)tile * BM * INPUT_SZ;
    int row = tid >> 3, c = tid & 7;
    cp16(sb + SM_X + (uint32_t)((row * XSTR + c * 8) * 2),
         src0 + row * INPUT_SZ + c * 8);
}

// =================== main persistent kernel ==================================
extern "C" __global__ void __launch_bounds__(TPB, 1)
lstm_policy_mma(float* __restrict__ out_policy,
                float* __restrict__ out_value)
{
    extern __shared__ char smem[];
    const uint32_t sb = smem_u32(smem);
    const int tid  = threadIdx.x;
    const int lane = tid & 31;
    const int wid  = tid >> 5;
    const int mg   = wid >> 2;         // 0..3 : 16-row m-group
    const int jqw  = wid & 3;          // 0..3 : 32-col j-quarter

    float* b0_s = reinterpret_cast<float*>(smem + SM_B0);
    float* b1_s = reinterpret_cast<float*>(smem + SM_B1);
    float* bp_s = reinterpret_cast<float*>(smem + SM_BP);
    float* bv_s = reinterpret_cast<float*>(smem + SM_BV);

    const int rA   = lane & 15;
    const int kA   = ((lane >> 4) & 1) * 8;
    const int rB   = (lane & 7) + ((lane >> 4) & 1) * 8;
    const int kB   = ((lane >> 3) & 1) * 8;
    const int qr   = lane >> 2;
    const int qc   = (lane & 3) * 2;

    // ===== prologue: group A = W0 + x(first tile); group B = W1 + WH =====
#pragma unroll
    for (int it = 0; it < 6; it++) {               // W0: 3072 16B chunks
        int id = tid + it * TPB;
        int rr = id >> 3, c = id & 7;
        cp16(sb + SM_W0 + (uint32_t)((rr * W0STR + c * 8) * 2),
             gW0h + rr * 64 + c * 8);
    }
    stage_x(sb, blockIdx.x, tid);
    cp_commit();                                   // group A
#pragma unroll
    for (int it = 0; it < 12; it++) {              // W1: 6144 chunks
        int id = tid + it * TPB;
        int rr = id >> 4, c = id & 15;
        cp16(sb + SM_W1 + (uint32_t)((rr * W1STR + c * 8) * 2),
             gW1h + rr * 128 + c * 8);
    }
    {                                              // WH: 512 chunks
        int row = tid >> 4, c = tid & 15;
        cp16(sb + SM_WH + (uint32_t)((row * WHSTR + c * 8) * 2),
             gWHh + row * 128 + c * 8);
    }
    cp_commit();                                   // group B

    if (tid < 384) {
        b0_s[tid] = gB0[tid];
        b1_s[tid] = gB1[tid];
    }
    if (tid < NUM_ACT) bp_s[tid] = gBP[tid];
    if (tid == 0) bv_s[0] = gBV[0];

    cp_wait<1>();          // group A done: W0 + x0 resident
    __syncthreads();

    // =================== persistent tile loop ===================
    for (int t = blockIdx.x; t < NTILES; t += NCTA) {
        const int base = t * BM;
        const int tn   = t + NCTA;

        // ---- layer 0: gates = x @ W0^T -> h0 smem ----
        {
            float acc[3][4][4];
#pragma unroll
            for (int g = 0; g < 3; g++)
#pragma unroll
                for (int jt = 0; jt < 4; jt++)
#pragma unroll
                    for (int e = 0; e < 4; e++) acc[g][jt][e] = 0.f;

#pragma unroll
            for (int ks = 0; ks < 4; ks++) {
                uint32_t a[4];
                {
                    uint32_t addr = sb + SM_X +
                        (uint32_t)(((mg * 16 + rA) * XSTR + ks * 16 + kA) * 2);
                    ldsm4(a[0], a[1], a[2], a[3], addr);
                }
#pragma unroll
                for (int g = 0; g < 3; g++) {
#pragma unroll
                    for (int jp = 0; jp < 2; jp++) {
                        int jb = jqw * 32 + jp * 16;
                        uint32_t addr = sb + SM_W0 +
                            (uint32_t)(((g * 128 + jb + rB) * W0STR + ks * 16 + kB) * 2);
                        uint32_t b0, b1, b2, b3;
                        ldsm4(b0, b1, b2, b3, addr);
                        mma16816(acc[g][2 * jp],     a, b0, b1);
                        mma16816(acc[g][2 * jp + 1], a, b2, b3);
                    }
                }
            }
#pragma unroll
            for (int jt = 0; jt < 4; jt++) {
                int j0 = jqw * 32 + jt * 8 + qc;
                float2 bi = *reinterpret_cast<const float2*>(b0_s + j0);
                float2 bg = *reinterpret_cast<const float2*>(b0_s + 128 + j0);
                float2 bo = *reinterpret_cast<const float2*>(b0_s + 256 + j0);
                float v0 = hcell(acc[0][jt][0] + bi.x, acc[1][jt][0] + bg.x,
                                 acc[2][jt][0] + bo.x);
                float v1 = hcell(acc[0][jt][1] + bi.y, acc[1][jt][1] + bg.y,
                                 acc[2][jt][1] + bo.y);
                float v2 = hcell(acc[0][jt][2] + bi.x, acc[1][jt][2] + bg.x,
                                 acc[2][jt][2] + bo.x);
                float v3 = hcell(acc[0][jt][3] + bi.y, acc[1][jt][3] + bg.y,
                                 acc[2][jt][3] + bo.y);
                int ra = mg * 16 + qr;
                *reinterpret_cast<uint32_t*>(smem + SM_H0 + (ra * HSTR + j0) * 2)
                    = h2u(v0, v1);
                *reinterpret_cast<uint32_t*>(smem + SM_H0 + ((ra + 8) * HSTR + j0) * 2)
                    = h2u(v2, v3);
            }
        }
        __syncthreads();       // X fully read, H0 complete

        // ---- prefetch next tile's x (overlaps layer1+heads) ----
        if (tn < NTILES) {
            stage_x(sb, tn, tid);
            cp_commit();
        }
        cp_wait<1>();          // first tile: ensures group B (W1+WH); later: no-op
        __syncthreads();

        // ---- layer 1 + h1 as in-register A-frags ----
        uint32_t hfrag[2][4];   // [kt-in-quarter][4]
        {
            float acc[3][4][4];
#pragma unroll
            for (int g = 0; g < 3; g++)
#pragma unroll
                for (int jt = 0; jt < 4; jt++)
#pragma unroll
                    for (int e = 0; e < 4; e++) acc[g][jt][e] = 0.f;

#pragma unroll
            for (int ks = 0; ks < 8; ks++) {
                uint32_t a[4];
                {
                    uint32_t addr = sb + SM_H0 +
                        (uint32_t)(((mg * 16 + rA) * HSTR + ks * 16 + kA) * 2);
                    ldsm4(a[0], a[1], a[2], a[3], addr);
                }
#pragma unroll
                for (int g = 0; g < 3; g++) {
#pragma unroll
                    for (int jp = 0; jp < 2; jp++) {
                        int jb = jqw * 32 + jp * 16;
                        uint32_t addr = sb + SM_W1 +
                            (uint32_t)(((g * 128 + jb + rB) * W1STR + ks * 16 + kB) * 2);
                        uint32_t b0, b1, b2, b3;
                        ldsm4(b0, b1, b2, b3, addr);
                        mma16816(acc[g][2 * jp],     a, b0, b1);
                        mma16816(acc[g][2 * jp + 1], a, b2, b3);
                    }
                }
            }
            // epilogue: hcell -> packed A-fragments (kt = jp)
#pragma unroll
            for (int jp = 0; jp < 2; jp++) {
                float v[2][4];
#pragma unroll
                for (int half = 0; half < 2; half++) {
                    int jt = 2 * jp + half;
                    int j0 = jqw * 32 + jt * 8 + qc;
                    float2 bi = *reinterpret_cast<const float2*>(b1_s + j0);
                    float2 bg = *reinterpret_cast<const float2*>(b1_s + 128 + j0);
                    float2 bo = *reinterpret_cast<const float2*>(b1_s + 256 + j0);
                    v[half][0] = hcell(acc[0][jt][0] + bi.x, acc[1][jt][0] + bg.x,
                                       acc[2][jt][0] + bo.x);
                    v[half][1] = hcell(acc[0][jt][1] + bi.y, acc[1][jt][1] + bg.y,
                                       acc[2][jt][1] + bo.y);
                    v[half][2] = hcell(acc[0][jt][2] + bi.x, acc[1][jt][2] + bg.x,
                                       acc[2][jt][2] + bo.x);
                    v[half][3] = hcell(acc[0][jt][3] + bi.y, acc[1][jt][3] + bg.y,
                                       acc[2][jt][3] + bo.y);
                }
                hfrag[jp][0] = h2u(v[0][0], v[0][1]);
                hfrag[jp][1] = h2u(v[0][2], v[0][3]);
                hfrag[jp][2] = h2u(v[1][0], v[1][1]);
                hfrag[jp][3] = h2u(v[1][2], v[1][3]);
            }
        }

        // ---- heads: partial [m x 17] over this warp's 32-k chunk ----
        float hacc[3][4];
#pragma unroll
        for (int nt = 0; nt < 3; nt++)
#pragma unroll
            for (int e = 0; e < 4; e++) hacc[nt][e] = 0.f;

#pragma unroll
        for (int kt = 0; kt < 2; kt++) {
            int kg = jqw * 32 + kt * 16;
            uint32_t b0, b1, b2, b3, c0, c1;
            uint32_t addr01 = sb + SM_WH + (uint32_t)(((rB) * WHSTR + kg + kB) * 2);
            ldsm4(b0, b1, b2, b3, addr01);
            uint32_t addr2 = sb + SM_WH +
                (uint32_t)(((16 + (lane & 7)) * WHSTR + kg + ((lane >> 3) & 1) * 8) * 2);
            ldsm2(c0, c1, addr2);
            mma16816(hacc[0], hfrag[kt], b0, b1);
            mma16816(hacc[1], hfrag[kt], b2, b3);
            mma16816(hacc[2], hfrag[kt], c0, c1);
        }

        // ---- 4-way cross-warp (j-quarter) reduction (BUF aliases H0) ----
        __syncthreads();       // all H0 reads done -> alias safe
        float* buf = reinterpret_cast<float*>(smem + SM_BUF);
#pragma unroll
        for (int nt = 0; nt < 3; nt++)
#pragma unroll
            for (int e = 0; e < 4; e++) {
                int n = nt * 8 + qc + (e & 1);
                if (n < 17) {
                    int m = mg * 16 + qr + ((e >= 2) ? 8 : 0);
                    buf[(jqw * BM + m) * BUFSTR + n] = hacc[nt][e];
                }
            }
        __syncthreads();

        if (tid < 2 * BM) {
            int row = tid >> 1, hn = tid & 1;
            float s[8];
#pragma unroll
            for (int c = 0; c < 8; c++) s[c] = bp_s[hn * 8 + c];
#pragma unroll
            for (int q = 0; q < 4; q++) {
                const float* src = buf + (q * BM + row) * BUFSTR + hn * 8;
#pragma unroll
                for (int c = 0; c < 8; c++) s[c] += src[c];
            }
            float4* dst = reinterpret_cast<float4*>(
                out_policy + (size_t)(base + row) * NUM_ACT + hn * 8);
            dst[0] = make_float4(s[0], s[1], s[2], s[3]);
            dst[1] = make_float4(s[4], s[5], s[6], s[7]);
        } else if (tid < 3 * BM) {
            int row = tid - 2 * BM;
            float v = bv_s[0];
#pragma unroll
            for (int q = 0; q < 4; q++) v += buf[(q * BM + row) * BUFSTR + 16];
            out_value[base + row] = v;
        }

        if (tn < NTILES) {
            cp_wait<0>();      // next x tile resident
            __syncthreads();   // visibility of copies + BUF->H0 reuse
        }
    }
}

extern "C" void kernel_launch(void* const* d_in, const int* in_sizes, int n_in,
                              void* d_out, int out_size)
{
    (void)in_sizes; (void)n_in; (void)out_size;
    // 0:x 1:Wih0 2:Whh0(dead) 3:bih0 4:bhh0 5:Wih1 6:Whh1(dead) 7:bih1 8:bhh1
    // 9:Wp 10:bp 11:Wv 12:bv
    const float* x    = (const float*)d_in[0];
    const float* Wih0 = (const float*)d_in[1];
    const float* bih0 = (const float*)d_in[3];
    const float* bhh0 = (const float*)d_in[4];
    const float* Wih1 = (const float*)d_in[5];
    const float* bih1 = (const float*)d_in[7];
    const float* bhh1 = (const float*)d_in[8];
    const float* Wp   = (const float*)d_in[9];
    const float* bp   = (const float*)d_in[10];
    const float* Wv   = (const float*)d_in[11];
    const float* bv   = (const float*)d_in[12];

    float* out        = (float*)d_out;
    float* out_policy = out;
    float* out_value  = out + (size_t)BATCH_N * NUM_ACT;

    prep_weights<<<512, 256>>>(x, Wih0, Wih1, Wp, Wv,
                               bih0, bhh0, bih1, bhh1, bp, bv);

    cudaFuncSetAttribute((const void*)lstm_policy_mma,
                         cudaFuncAttributeMaxDynamicSharedMemorySize, SM_TOTAL);
    lstm_policy_mma<<<NCTA, TPB, SM_TOTAL>>>(out_policy, out_value);
}

// round 12
// speedup vs baseline: 1.2159x; 1.2159x over previous
#include <cuda_runtime.h>
#include <cuda_fp16.h>
#include <cstdint>
#include <math.h>

#define HIDDEN    128
#define INPUT_SZ  64
#define NUM_ACT   16
#define BATCH_N   65536
#define TPB       512
#define BM        128
#define NTILES    (BATCH_N / BM)      // 512
#define NCTA      148

// padded strides (in halfs) -> conflict-free ldmatrix
#define XSTR   72
#define W0STR  72
#define W1STR  136
#define WHSTR  136
#define HSTR   136
#define BUFSTR 17                      // exact-fit head reduce buffer (floats)

// smem layout (bytes)
#define SM_X    0                      // 128*72*2   = 18432 (live every tile: prefetch target)
#define SM_W0   18432                  // 3*128*72*2 = 55296
#define SM_W1   73728                  // 3*128*136*2= 104448
#define SM_WH   178176                 // 32*136*2   = 8704
#define SM_H0   186880                 // 128*136*2  = 34816
#define SM_BUF  186880                 // [4][128][17] f32 = 34816 (aliases H0, dead at reduce)
#define SM_B0   221696
#define SM_B1   223232
#define SM_BP   224768
#define SM_BV   224832
#define SM_TOTAL 224896

// ---------------- precomputed fp16 tensors / f32 bias sums (device globals) --
__device__ __half gW0h[3 * 128 * 64];     // [g*128+j][64]
__device__ __half gW1h[3 * 128 * 128];    // [g*128+j][128]
__device__ __half gWHh[32 * 128];         // rows 0-15 Wp, 16 Wv, 17-31 zero
__device__ __half gXh[BATCH_N * INPUT_SZ];// x pre-converted to fp16
__device__ float  gB0[384], gB1[384], gBP[16], gBV[1];

__device__ __forceinline__ uint32_t smem_u32(const void* p) {
    uint32_t a;
    asm("{ .reg .u64 t; cvta.to.shared.u64 t, %1; cvt.u32.u64 %0, t; }"
        : "=r"(a) : "l"(p));
    return a;
}
__device__ __forceinline__ void cp16(uint32_t dst, const void* src) {
    asm volatile("cp.async.cg.shared.global [%0], [%1], 16;"
                 :: "r"(dst), "l"(src));
}
__device__ __forceinline__ void cp_commit() {
    asm volatile("cp.async.commit_group;" ::: "memory");
}
template <int N>
__device__ __forceinline__ void cp_wait() {
    asm volatile("cp.async.wait_group %0;" :: "n"(N) : "memory");
}
__device__ __forceinline__ void ldsm4(uint32_t& r0, uint32_t& r1, uint32_t& r2,
                                      uint32_t& r3, uint32_t addr) {
    asm volatile("ldmatrix.sync.aligned.m8n8.x4.shared.b16 {%0,%1,%2,%3}, [%4];"
                 : "=r"(r0), "=r"(r1), "=r"(r2), "=r"(r3) : "r"(addr));
}
__device__ __forceinline__ void ldsm2(uint32_t& r0, uint32_t& r1, uint32_t addr) {
    asm volatile("ldmatrix.sync.aligned.m8n8.x2.shared.b16 {%0,%1}, [%2];"
                 : "=r"(r0), "=r"(r1) : "r"(addr));
}
__device__ __forceinline__ void mma16816(float* d, const uint32_t* a,
                                         uint32_t b0, uint32_t b1) {
    asm volatile(
        "mma.sync.aligned.m16n8k16.row.col.f32.f16.f16.f32 "
        "{%0,%1,%2,%3}, {%4,%5,%6,%7}, {%8,%9}, {%0,%1,%2,%3};"
        : "+f"(d[0]), "+f"(d[1]), "+f"(d[2]), "+f"(d[3])
        : "r"(a[0]), "r"(a[1]), "r"(a[2]), "r"(a[3]), "r"(b0), "r"(b1));
}

// MUFU.TANH hcell: 4 TANH, 0 RCP, no clamps.
// sig(x) = 0.5 + 0.5*tanh(x/2);  h = sig(o)*tanh(sig(i)*tanh(g))
__device__ __forceinline__ float ftanh_a(float x) {
    float y;
    asm("tanh.approx.f32 %0, %1;" : "=f"(y) : "f"(x));
    return y;
}
__device__ __forceinline__ float hcell(float i, float g, float o) {
    float si = fmaf(0.5f, ftanh_a(0.5f * i), 0.5f);
    float tg = ftanh_a(g);
    float tc = ftanh_a(si * tg);
    float so = fmaf(0.5f, ftanh_a(0.5f * o), 0.5f);
    return so * tc;
}
__device__ __forceinline__ int grow_of(int g) {   // live gates i,g,o in 4H blocks
    return (g == 0) ? 0 : (g == 1) ? 2 * HIDDEN : 3 * HIDDEN;
}
__device__ __forceinline__ uint32_t h2u(float a, float b) {
    __half2 h = __floats2half2_rn(a, b);
    return *reinterpret_cast<uint32_t*>(&h);
}

// =================== prep kernel: fp32 -> fp16 weights + x, bias sums ========
extern "C" __global__ void prep_weights(const float* __restrict__ x,
                                        const float* __restrict__ Wih0,
                                        const float* __restrict__ Wih1,
                                        const float* __restrict__ Wp,
                                        const float* __restrict__ Wv,
                                        const float* __restrict__ bih0,
                                        const float* __restrict__ bhh0,
                                        const float* __restrict__ bih1,
                                        const float* __restrict__ bhh1,
                                        const float* __restrict__ bp,
                                        const float* __restrict__ bv)
{
    const int tid = blockIdx.x * blockDim.x + threadIdx.x;
    const int nt  = gridDim.x * blockDim.x;
    const int NX8 = BATCH_N * INPUT_SZ / 8;
    for (int idx = tid; idx < NX8; idx += nt) {
        const float4* src = reinterpret_cast<const float4*>(x) + 2 * idx;
        float4 a = __ldg(src), b = __ldg(src + 1);
        uint4 u = make_uint4(h2u(a.x, a.y), h2u(a.z, a.w), h2u(b.x, b.y), h2u(b.z, b.w));
        *(reinterpret_cast<uint4*>(gXh) + idx) = u;
    }
    for (int idx = tid; idx < 3 * 128 * 64; idx += nt) {
        int rr = idx >> 6, c = idx & 63;
        int g = rr >> 7, j = rr & 127;
        gW0h[idx] = __float2half_rn(__ldg(Wih0 + (size_t)(grow_of(g) + j) * 64 + c));
    }
    for (int idx = tid; idx < 3 * 128 * 128; idx += nt) {
        int rr = idx >> 7, c = idx & 127;
        int g = rr >> 7, j = rr & 127;
        gW1h[idx] = __float2half_rn(__ldg(Wih1 + (size_t)(grow_of(g) + j) * 128 + c));
    }
    for (int idx = tid; idx < 32 * 128; idx += nt) {
        int row = idx >> 7, c = idx & 127;
        float v = (row < NUM_ACT) ? __ldg(Wp + row * 128 + c)
                : (row == NUM_ACT) ? __ldg(Wv + c) : 0.0f;
        gWHh[idx] = __float2half_rn(v);
    }
    for (int idx = tid; idx < 384; idx += nt) {
        int g = idx >> 7, j = idx & 127;
        int row = grow_of(g) + j;
        gB0[idx] = __ldg(bih0 + row) + __ldg(bhh0 + row);
        gB1[idx] = __ldg(bih1 + row) + __ldg(bhh1 + row);
    }
    if (tid < NUM_ACT) gBP[tid] = __ldg(bp + tid);
    if (tid == 0) gBV[0] = __ldg(bv);
}

// x tile -> smem via cp.async (1024 16B chunks; 2 per thread)
__device__ __forceinline__ void stage_x(uint32_t sb, int tile, int tid) {
    const __half* src0 = gXh + (size_t)tile * BM * INPUT_SZ;
#pragma unroll
    for (int it = 0; it < 2; it++) {
        int id = tid + it * TPB;
        int row = id >> 3, c = id & 7;
        cp16(sb + SM_X + (uint32_t)((row * XSTR + c * 8) * 2),
             src0 + row * INPUT_SZ + c * 8);
    }
}

// =================== main persistent kernel ==================================
extern "C" __global__ void __launch_bounds__(TPB, 1)
lstm_policy_mma(float* __restrict__ out_policy,
                float* __restrict__ out_value)
{
    extern __shared__ char smem[];
    const uint32_t sb = smem_u32(smem);
    const int tid  = threadIdx.x;
    const int lane = tid & 31;
    const int wid  = tid >> 5;
    const int mg   = wid >> 2;         // 0..3 : 32-row m-group
    const int jqw  = wid & 3;          // 0..3 : 32-col j-quarter

    float* b0_s = reinterpret_cast<float*>(smem + SM_B0);
    float* b1_s = reinterpret_cast<float*>(smem + SM_B1);
    float* bp_s = reinterpret_cast<float*>(smem + SM_BP);
    float* bv_s = reinterpret_cast<float*>(smem + SM_BV);

    const int rA   = lane & 15;
    const int kA   = ((lane >> 4) & 1) * 8;
    const int rB   = (lane & 7) + ((lane >> 4) & 1) * 8;
    const int kB   = ((lane >> 3) & 1) * 8;
    const int qr   = lane >> 2;
    const int qc   = (lane & 3) * 2;

    // ===== prologue: group A = W0 + x(first tile); group B = W1 + WH =====
#pragma unroll
    for (int it = 0; it < 6; it++) {               // W0: 3072 16B chunks
        int id = tid + it * TPB;
        int rr = id >> 3, c = id & 7;
        cp16(sb + SM_W0 + (uint32_t)((rr * W0STR + c * 8) * 2),
             gW0h + rr * 64 + c * 8);
    }
    stage_x(sb, blockIdx.x, tid);
    cp_commit();                                   // group A
#pragma unroll
    for (int it = 0; it < 12; it++) {              // W1: 6144 chunks
        int id = tid + it * TPB;
        int rr = id >> 4, c = id & 15;
        cp16(sb + SM_W1 + (uint32_t)((rr * W1STR + c * 8) * 2),
             gW1h + rr * 128 + c * 8);
    }
    {                                              // WH: 512 chunks
        int row = tid >> 4, c = tid & 15;
        cp16(sb + SM_WH + (uint32_t)((row * WHSTR + c * 8) * 2),
             gWHh + row * 128 + c * 8);
    }
    cp_commit();                                   // group B

    if (tid < 384) {
        b0_s[tid] = gB0[tid];
        b1_s[tid] = gB1[tid];
    }
    if (tid < NUM_ACT) bp_s[tid] = gBP[tid];
    if (tid == 0) bv_s[0] = gBV[0];

    cp_wait<1>();          // group A done: W0 + x0 resident
    __syncthreads();

    // =================== persistent tile loop ===================
    for (int t = blockIdx.x; t < NTILES; t += NCTA) {
        const int base = t * BM;
        const int tn   = t + NCTA;

        // ---- layer 0: gates = x @ W0^T -> h0 smem ----
        {
            float acc[2][3][4][4];
#pragma unroll
            for (int mt = 0; mt < 2; mt++)
#pragma unroll
                for (int g = 0; g < 3; g++)
#pragma unroll
                    for (int jt = 0; jt < 4; jt++)
#pragma unroll
                        for (int e = 0; e < 4; e++) acc[mt][g][jt][e] = 0.f;

#pragma unroll 2
            for (int ks = 0; ks < 4; ks++) {
                uint32_t a[2][4];
#pragma unroll
                for (int mt = 0; mt < 2; mt++) {
                    uint32_t addr = sb + SM_X +
                        (uint32_t)(((mg * 32 + mt * 16 + rA) * XSTR + ks * 16 + kA) * 2);
                    ldsm4(a[mt][0], a[mt][1], a[mt][2], a[mt][3], addr);
                }
#pragma unroll
                for (int g = 0; g < 3; g++) {
#pragma unroll
                    for (int jp = 0; jp < 2; jp++) {
                        int jb = jqw * 32 + jp * 16;
                        uint32_t addr = sb + SM_W0 +
                            (uint32_t)(((g * 128 + jb + rB) * W0STR + ks * 16 + kB) * 2);
                        uint32_t b0, b1, b2, b3;
                        ldsm4(b0, b1, b2, b3, addr);
#pragma unroll
                        for (int mt = 0; mt < 2; mt++) {
                            mma16816(acc[mt][g][2 * jp],     a[mt], b0, b1);
                            mma16816(acc[mt][g][2 * jp + 1], a[mt], b2, b3);
                        }
                    }
                }
            }
#pragma unroll
            for (int mt = 0; mt < 2; mt++) {
#pragma unroll
                for (int jt = 0; jt < 4; jt++) {
                    int j0 = jqw * 32 + jt * 8 + qc;
                    float2 bi = *reinterpret_cast<const float2*>(b0_s + j0);
                    float2 bg = *reinterpret_cast<const float2*>(b0_s + 128 + j0);
                    float2 bo = *reinterpret_cast<const float2*>(b0_s + 256 + j0);
                    float v0 = hcell(acc[mt][0][jt][0] + bi.x, acc[mt][1][jt][0] + bg.x,
                                     acc[mt][2][jt][0] + bo.x);
                    float v1 = hcell(acc[mt][0][jt][1] + bi.y, acc[mt][1][jt][1] + bg.y,
                                     acc[mt][2][jt][1] + bo.y);
                    float v2 = hcell(acc[mt][0][jt][2] + bi.x, acc[mt][1][jt][2] + bg.x,
                                     acc[mt][2][jt][2] + bo.x);
                    float v3 = hcell(acc[mt][0][jt][3] + bi.y, acc[mt][1][jt][3] + bg.y,
                                     acc[mt][2][jt][3] + bo.y);
                    int ra = mg * 32 + mt * 16 + qr;
                    *reinterpret_cast<uint32_t*>(smem + SM_H0 + (ra * HSTR + j0) * 2)
                        = h2u(v0, v1);
                    *reinterpret_cast<uint32_t*>(smem + SM_H0 + ((ra + 8) * HSTR + j0) * 2)
                        = h2u(v2, v3);
                }
            }
        }
        __syncthreads();       // X fully read, H0 complete

        // ---- prefetch next tile's x into X buffer (overlaps layer1+heads) ----
        if (tn < NTILES) {
            stage_x(sb, tn, tid);
            cp_commit();
        }
        cp_wait<1>();          // first tile: ensures group B (W1+WH); later: no-op
        __syncthreads();

        // ---- layer 1 + h1 as in-register A-frags ----
        uint32_t hfrag[2][2][4];   // [mt][kt-in-quarter][4]
        {
            float acc[2][3][4][4];
#pragma unroll
            for (int mt = 0; mt < 2; mt++)
#pragma unroll
                for (int g = 0; g < 3; g++)
#pragma unroll
                    for (int jt = 0; jt < 4; jt++)
#pragma unroll
                        for (int e = 0; e < 4; e++) acc[mt][g][jt][e] = 0.f;

#pragma unroll 2
            for (int ks = 0; ks < 8; ks++) {
                uint32_t a[2][4];
#pragma unroll
                for (int mt = 0; mt < 2; mt++) {
                    uint32_t addr = sb + SM_H0 +
                        (uint32_t)(((mg * 32 + mt * 16 + rA) * HSTR + ks * 16 + kA) * 2);
                    ldsm4(a[mt][0], a[mt][1], a[mt][2], a[mt][3], addr);
                }
#pragma unroll
                for (int g = 0; g < 3; g++) {
#pragma unroll
                    for (int jp = 0; jp < 2; jp++) {
                        int jb = jqw * 32 + jp * 16;
                        uint32_t addr = sb + SM_W1 +
                            (uint32_t)(((g * 128 + jb + rB) * W1STR + ks * 16 + kB) * 2);
                        uint32_t b0, b1, b2, b3;
                        ldsm4(b0, b1, b2, b3, addr);
#pragma unroll
                        for (int mt = 0; mt < 2; mt++) {
                            mma16816(acc[mt][g][2 * jp],     a[mt], b0, b1);
                            mma16816(acc[mt][g][2 * jp + 1], a[mt], b2, b3);
                        }
                    }
                }
            }
            // epilogue: hcell -> packed A-fragments (kt = jp)
#pragma unroll
            for (int mt = 0; mt < 2; mt++) {
#pragma unroll
                for (int jp = 0; jp < 2; jp++) {
                    float v[2][4];
#pragma unroll
                    for (int half = 0; half < 2; half++) {
                        int jt = 2 * jp + half;
                        int j0 = jqw * 32 + jt * 8 + qc;
                        float2 bi = *reinterpret_cast<const float2*>(b1_s + j0);
                        float2 bg = *reinterpret_cast<const float2*>(b1_s + 128 + j0);
                        float2 bo = *reinterpret_cast<const float2*>(b1_s + 256 + j0);
                        v[half][0] = hcell(acc[mt][0][jt][0] + bi.x, acc[mt][1][jt][0] + bg.x,
                                           acc[mt][2][jt][0] + bo.x);
                        v[half][1] = hcell(acc[mt][0][jt][1] + bi.y, acc[mt][1][jt][1] + bg.y,
                                           acc[mt][2][jt][1] + bo.y);
                        v[half][2] = hcell(acc[mt][0][jt][2] + bi.x, acc[mt][1][jt][2] + bg.x,
                                           acc[mt][2][jt][2] + bo.x);
                        v[half][3] = hcell(acc[mt][0][jt][3] + bi.y, acc[mt][1][jt][3] + bg.y,
                                           acc[mt][2][jt][3] + bo.y);
                    }
                    hfrag[mt][jp][0] = h2u(v[0][0], v[0][1]);
                    hfrag[mt][jp][1] = h2u(v[0][2], v[0][3]);
                    hfrag[mt][jp][2] = h2u(v[1][0], v[1][1]);
                    hfrag[mt][jp][3] = h2u(v[1][2], v[1][3]);
                }
            }
        }

        // ---- heads: partial [m x 17] over this warp's 32-k chunk ----
        float hacc[2][3][4];
#pragma unroll
        for (int mt = 0; mt < 2; mt++)
#pragma unroll
            for (int nt = 0; nt < 3; nt++)
#pragma unroll
                for (int e = 0; e < 4; e++) hacc[mt][nt][e] = 0.f;

#pragma unroll
        for (int kt = 0; kt < 2; kt++) {
            int kg = jqw * 32 + kt * 16;
            uint32_t b0, b1, b2, b3, c0, c1;
            uint32_t addr01 = sb + SM_WH + (uint32_t)(((rB) * WHSTR + kg + kB) * 2);
            ldsm4(b0, b1, b2, b3, addr01);
            uint32_t addr2 = sb + SM_WH +
                (uint32_t)(((16 + (lane & 7)) * WHSTR + kg + ((lane >> 3) & 1) * 8) * 2);
            ldsm2(c0, c1, addr2);
#pragma unroll
            for (int mt = 0; mt < 2; mt++) {
                mma16816(hacc[mt][0], hfrag[mt][kt], b0, b1);
                mma16816(hacc[mt][1], hfrag[mt][kt], b2, b3);
                mma16816(hacc[mt][2], hfrag[mt][kt], c0, c1);
            }
        }

        // ---- 4-way cross-warp (j-quarter) reduction (BUF aliases H0) ----
        __syncthreads();       // all H0 reads done -> alias safe
        float* buf = reinterpret_cast<float*>(smem + SM_BUF);
#pragma unroll
        for (int mt = 0; mt < 2; mt++)
#pragma unroll
            for (int nt = 0; nt < 3; nt++)
#pragma unroll
                for (int e = 0; e < 4; e++) {
                    int n = nt * 8 + qc + (e & 1);
                    if (n < 17) {
                        int m = mg * 32 + mt * 16 + qr + ((e >= 2) ? 8 : 0);
                        buf[(jqw * BM + m) * BUFSTR + n] = hacc[mt][nt][e];
                    }
                }
        __syncthreads();

        if (tid < 2 * BM) {
            int row = tid >> 1, hn = tid & 1;
            float s[8];
#pragma unroll
            for (int c = 0; c < 8; c++) s[c] = bp_s[hn * 8 + c];
#pragma unroll
            for (int q = 0; q < 4; q++) {
                const float* src = buf + (q * BM + row) * BUFSTR + hn * 8;
#pragma unroll
                for (int c = 0; c < 8; c++) s[c] += src[c];
            }
            float4* dst = reinterpret_cast<float4*>(
                out_policy + (size_t)(base + row) * NUM_ACT + hn * 8);
            dst[0] = make_float4(s[0], s[1], s[2], s[3]);
            dst[1] = make_float4(s[4], s[5], s[6], s[7]);
        } else if (tid < 3 * BM) {
            int row = tid - 2 * BM;
            float v = bv_s[0];
#pragma unroll
            for (int q = 0; q < 4; q++) v += buf[(q * BM + row) * BUFSTR + 16];
            out_value[base + row] = v;
        }

        if (tn < NTILES) {
            cp_wait<0>();      // next x tile resident
            __syncthreads();   // visibility of copies + BUF->H0 reuse
        }
    }
}

extern "C" void kernel_launch(void* const* d_in, const int* in_sizes, int n_in,
                              void* d_out, int out_size)
{
    (void)in_sizes; (void)n_in; (void)out_size;
    // 0:x 1:Wih0 2:Whh0(dead) 3:bih0 4:bhh0 5:Wih1 6:Whh1(dead) 7:bih1 8:bhh1
    // 9:Wp 10:bp 11:Wv 12:bv
    const float* x    = (const float*)d_in[0];
    const float* Wih0 = (const float*)d_in[1];
    const float* bih0 = (const float*)d_in[3];
    const float* bhh0 = (const float*)d_in[4];
    const float* Wih1 = (const float*)d_in[5];
    const float* bih1 = (const float*)d_in[7];
    const float* bhh1 = (const float*)d_in[8];
    const float* Wp   = (const float*)d_in[9];
    const float* bp   = (const float*)d_in[10];
    const float* Wv   = (const float*)d_in[11];
    const float* bv   = (const float*)d_in[12];

    float* out        = (float*)d_out;
    float* out_policy = out;
    float* out_value  = out + (size_t)BATCH_N * NUM_ACT;

    prep_weights<<<512, 256>>>(x, Wih0, Wih1, Wp, Wv,
                               bih0, bhh0, bih1, bhh1, bp, bv);

    cudaFuncSetAttribute((const void*)lstm_policy_mma,
                         cudaFuncAttributeMaxDynamicSharedMemorySize, SM_TOTAL);
    lstm_policy_mma<<<NCTA, TPB, SM_TOTAL>>>(out_policy, out_value);
}

// round 13
// speedup vs baseline: 1.2208x; 1.0040x over previous
#include <cuda_runtime.h>
#include <cuda_fp16.h>
#include <cstdint>
#include <math.h>

#define HIDDEN    128
#define INPUT_SZ  64
#define NUM_ACT   16
#define BATCH_N   65536
#define TPB       512
#define BM        128
#define NTILES    (BATCH_N / BM)      // 512
#define NCTA      148

// padded strides (in halfs) -> conflict-free ldmatrix
#define XSTR   72
#define W0STR  72
#define W1STR  136
#define WHSTR  136
#define HSTR   136
#define BUFSTR 17                      // exact-fit head reduce buffer (floats)

// smem layout (bytes)
#define SM_X    0                      // 128*72*2   = 18432 (live every tile: prefetch target)
#define SM_W0   18432                  // 3*128*72*2 = 55296
#define SM_W1   73728                  // 3*128*136*2= 104448
#define SM_WH   178176                 // 32*136*2   = 8704
#define SM_H0   186880                 // 128*136*2  = 34816
#define SM_BUF  186880                 // [4][128][17] f32 = 34816 (aliases H0, dead at reduce)
#define SM_B0   221696
#define SM_B1   223232
#define SM_BP   224768
#define SM_BV   224832
#define SM_TOTAL 224896

// ---------------- precomputed fp16 tensors / f32 bias sums (device globals) --
__device__ __half gW0h[3 * 128 * 64];     // [g*128+j][64]
__device__ __half gW1h[3 * 128 * 128];    // [g*128+j][128]
__device__ __half gWHh[32 * 128];         // rows 0-15 Wp, 16 Wv, 17-31 zero
__device__ __half gXh[BATCH_N * INPUT_SZ];// x pre-converted to fp16
__device__ float  gB0[384], gB1[384], gBP[16], gBV[1];

__device__ __forceinline__ uint32_t smem_u32(const void* p) {
    uint32_t a;
    asm("{ .reg .u64 t; cvta.to.shared.u64 t, %1; cvt.u32.u64 %0, t; }"
        : "=r"(a) : "l"(p));
    return a;
}
__device__ __forceinline__ void cp16(uint32_t dst, const void* src) {
    asm volatile("cp.async.cg.shared.global [%0], [%1], 16;"
                 :: "r"(dst), "l"(src));
}
__device__ __forceinline__ void cp_commit() {
    asm volatile("cp.async.commit_group;" ::: "memory");
}
template <int N>
__device__ __forceinline__ void cp_wait() {
    asm volatile("cp.async.wait_group %0;" :: "n"(N) : "memory");
}
__device__ __forceinline__ void ldsm4(uint32_t& r0, uint32_t& r1, uint32_t& r2,
                                      uint32_t& r3, uint32_t addr) {
    asm volatile("ldmatrix.sync.aligned.m8n8.x4.shared.b16 {%0,%1,%2,%3}, [%4];"
                 : "=r"(r0), "=r"(r1), "=r"(r2), "=r"(r3) : "r"(addr));
}
__device__ __forceinline__ void ldsm2(uint32_t& r0, uint32_t& r1, uint32_t addr) {
    asm volatile("ldmatrix.sync.aligned.m8n8.x2.shared.b16 {%0,%1}, [%2];"
                 : "=r"(r0), "=r"(r1) : "r"(addr));
}
__device__ __forceinline__ void mma16816(float* d, const uint32_t* a,
                                         uint32_t b0, uint32_t b1) {
    asm volatile(
        "mma.sync.aligned.m16n8k16.row.col.f32.f16.f16.f32 "
        "{%0,%1,%2,%3}, {%4,%5,%6,%7}, {%8,%9}, {%0,%1,%2,%3};"
        : "+f"(d[0]), "+f"(d[1]), "+f"(d[2]), "+f"(d[3])
        : "r"(a[0]), "r"(a[1]), "r"(a[2]), "r"(a[3]), "r"(b0), "r"(b1));
}

// ---------------- fp16x2 activation path ----------------
// tanh.approx.f16x2: one MUFU op = 2 values
__device__ __forceinline__ __half2 tanh2(__half2 x) {
    uint32_t xi = *reinterpret_cast<uint32_t*>(&x), yi;
    asm("tanh.approx.f16x2 %0, %1;" : "=r"(yi) : "r"(xi));
    return *reinterpret_cast<__half2*>(&yi);
}
__device__ __forceinline__ uint32_t h2u(float a, float b) {
    __half2 h = __floats2half2_rn(a, b);
    return *reinterpret_cast<uint32_t*>(&h);
}
// packed pair hcell: i,g,o pairs -> h pair (fp16x2, ready for smem/hfrag)
// sig(x) = 0.5 + 0.5*tanh(x/2);  h = sig(o)*tanh(sig(i)*tanh(g))
__device__ __forceinline__ uint32_t hcell2(uint32_t i2u, uint32_t g2u, uint32_t o2u) {
    const __half2 H = __half2(__half_raw{0x3800}, __half_raw{0x3800});   // (0.5, 0.5)
    __half2 i2 = *reinterpret_cast<__half2*>(&i2u);
    __half2 g2 = *reinterpret_cast<__half2*>(&g2u);
    __half2 o2 = *reinterpret_cast<__half2*>(&o2u);
    __half2 si = __hfma2(tanh2(__hmul2(i2, H)), H, H);
    __half2 tg = tanh2(g2);
    __half2 tc = tanh2(__hmul2(si, tg));
    __half2 so = __hfma2(tanh2(__hmul2(o2, H)), H, H);
    __half2 h  = __hmul2(so, tc);
    return *reinterpret_cast<uint32_t*>(&h);
}
__device__ __forceinline__ int grow_of(int g) {   // live gates i,g,o in 4H blocks
    return (g == 0) ? 0 : (g == 1) ? 2 * HIDDEN : 3 * HIDDEN;
}

// =================== prep kernel: fp32 -> fp16 weights + x, bias sums ========
extern "C" __global__ void prep_weights(const float* __restrict__ x,
                                        const float* __restrict__ Wih0,
                                        const float* __restrict__ Wih1,
                                        const float* __restrict__ Wp,
                                        const float* __restrict__ Wv,
                                        const float* __restrict__ bih0,
                                        const float* __restrict__ bhh0,
                                        const float* __restrict__ bih1,
                                        const float* __restrict__ bhh1,
                                        const float* __restrict__ bp,
                                        const float* __restrict__ bv)
{
    const int tid = blockIdx.x * blockDim.x + threadIdx.x;
    const int nt  = gridDim.x * blockDim.x;
    const int NX8 = BATCH_N * INPUT_SZ / 8;
    for (int idx = tid; idx < NX8; idx += nt) {
        const float4* src = reinterpret_cast<const float4*>(x) + 2 * idx;
        float4 a = __ldg(src), b = __ldg(src + 1);
        uint4 u = make_uint4(h2u(a.x, a.y), h2u(a.z, a.w), h2u(b.x, b.y), h2u(b.z, b.w));
        *(reinterpret_cast<uint4*>(gXh) + idx) = u;
    }
    for (int idx = tid; idx < 3 * 128 * 64; idx += nt) {
        int rr = idx >> 6, c = idx & 63;
        int g = rr >> 7, j = rr & 127;
        gW0h[idx] = __float2half_rn(__ldg(Wih0 + (size_t)(grow_of(g) + j) * 64 + c));
    }
    for (int idx = tid; idx < 3 * 128 * 128; idx += nt) {
        int rr = idx >> 7, c = idx & 127;
        int g = rr >> 7, j = rr & 127;
        gW1h[idx] = __float2half_rn(__ldg(Wih1 + (size_t)(grow_of(g) + j) * 128 + c));
    }
    for (int idx = tid; idx < 32 * 128; idx += nt) {
        int row = idx >> 7, c = idx & 127;
        float v = (row < NUM_ACT) ? __ldg(Wp + row * 128 + c)
                : (row == NUM_ACT) ? __ldg(Wv + c) : 0.0f;
        gWHh[idx] = __float2half_rn(v);
    }
    for (int idx = tid; idx < 384; idx += nt) {
        int g = idx >> 7, j = idx & 127;
        int row = grow_of(g) + j;
        gB0[idx] = __ldg(bih0 + row) + __ldg(bhh0 + row);
        gB1[idx] = __ldg(bih1 + row) + __ldg(bhh1 + row);
    }
    if (tid < NUM_ACT) gBP[tid] = __ldg(bp + tid);
    if (tid == 0) gBV[0] = __ldg(bv);
}

// x tile -> smem via cp.async (1024 16B chunks; 2 per thread)
__device__ __forceinline__ void stage_x(uint32_t sb, int tile, int tid) {
    const __half* src0 = gXh + (size_t)tile * BM * INPUT_SZ;
#pragma unroll
    for (int it = 0; it < 2; it++) {
        int id = tid + it * TPB;
        int row = id >> 3, c = id & 7;
        cp16(sb + SM_X + (uint32_t)((row * XSTR + c * 8) * 2),
             src0 + row * INPUT_SZ + c * 8);
    }
}

// =================== main persistent kernel ==================================
extern "C" __global__ void __launch_bounds__(TPB, 1)
lstm_policy_mma(float* __restrict__ out_policy,
                float* __restrict__ out_value)
{
    extern __shared__ char smem[];
    const uint32_t sb = smem_u32(smem);
    const int tid  = threadIdx.x;
    const int lane = tid & 31;
    const int wid  = tid >> 5;
    const int mg   = wid >> 2;         // 0..3 : 32-row m-group
    const int jqw  = wid & 3;          // 0..3 : 32-col j-quarter

    float* b0_s = reinterpret_cast<float*>(smem + SM_B0);
    float* b1_s = reinterpret_cast<float*>(smem + SM_B1);
    float* bp_s = reinterpret_cast<float*>(smem + SM_BP);
    float* bv_s = reinterpret_cast<float*>(smem + SM_BV);

    const int rA   = lane & 15;
    const int kA   = ((lane >> 4) & 1) * 8;
    const int rB   = (lane & 7) + ((lane >> 4) & 1) * 8;
    const int kB   = ((lane >> 3) & 1) * 8;
    const int qr   = lane >> 2;
    const int qc   = (lane & 3) * 2;

    // ===== prologue: group A = W0 + x(first tile); group B = W1 + WH =====
#pragma unroll
    for (int it = 0; it < 6; it++) {               // W0: 3072 16B chunks
        int id = tid + it * TPB;
        int rr = id >> 3, c = id & 7;
        cp16(sb + SM_W0 + (uint32_t)((rr * W0STR + c * 8) * 2),
             gW0h + rr * 64 + c * 8);
    }
    stage_x(sb, blockIdx.x, tid);
    cp_commit();                                   // group A
#pragma unroll
    for (int it = 0; it < 12; it++) {              // W1: 6144 chunks
        int id = tid + it * TPB;
        int rr = id >> 4, c = id & 15;
        cp16(sb + SM_W1 + (uint32_t)((rr * W1STR + c * 8) * 2),
             gW1h + rr * 128 + c * 8);
    }
    {                                              // WH: 512 chunks
        int row = tid >> 4, c = tid & 15;
        cp16(sb + SM_WH + (uint32_t)((row * WHSTR + c * 8) * 2),
             gWHh + row * 128 + c * 8);
    }
    cp_commit();                                   // group B

    if (tid < 384) {
        b0_s[tid] = gB0[tid];
        b1_s[tid] = gB1[tid];
    }
    if (tid < NUM_ACT) bp_s[tid] = gBP[tid];
    if (tid == 0) bv_s[0] = gBV[0];

    cp_wait<1>();          // group A done: W0 + x0 resident
    __syncthreads();

    // =================== persistent tile loop ===================
    for (int t = blockIdx.x; t < NTILES; t += NCTA) {
        const int base = t * BM;
        const int tn   = t + NCTA;

        // ---- layer 0: gates = x @ W0^T -> h0 smem ----
        {
            float acc[2][3][4][4];
#pragma unroll
            for (int mt = 0; mt < 2; mt++)
#pragma unroll
                for (int g = 0; g < 3; g++)
#pragma unroll
                    for (int jt = 0; jt < 4; jt++)
#pragma unroll
                        for (int e = 0; e < 4; e++) acc[mt][g][jt][e] = 0.f;

#pragma unroll 2
            for (int ks = 0; ks < 4; ks++) {
                uint32_t a[2][4];
#pragma unroll
                for (int mt = 0; mt < 2; mt++) {
                    uint32_t addr = sb + SM_X +
                        (uint32_t)(((mg * 32 + mt * 16 + rA) * XSTR + ks * 16 + kA) * 2);
                    ldsm4(a[mt][0], a[mt][1], a[mt][2], a[mt][3], addr);
                }
#pragma unroll
                for (int g = 0; g < 3; g++) {
#pragma unroll
                    for (int jp = 0; jp < 2; jp++) {
                        int jb = jqw * 32 + jp * 16;
                        uint32_t addr = sb + SM_W0 +
                            (uint32_t)(((g * 128 + jb + rB) * W0STR + ks * 16 + kB) * 2);
                        uint32_t b0, b1, b2, b3;
                        ldsm4(b0, b1, b2, b3, addr);
#pragma unroll
                        for (int mt = 0; mt < 2; mt++) {
                            mma16816(acc[mt][g][2 * jp],     a[mt], b0, b1);
                            mma16816(acc[mt][g][2 * jp + 1], a[mt], b2, b3);
                        }
                    }
                }
            }
#pragma unroll
            for (int mt = 0; mt < 2; mt++) {
#pragma unroll
                for (int jt = 0; jt < 4; jt++) {
                    int j0 = jqw * 32 + jt * 8 + qc;
                    float2 bi = *reinterpret_cast<const float2*>(b0_s + j0);
                    float2 bg = *reinterpret_cast<const float2*>(b0_s + 128 + j0);
                    float2 bo = *reinterpret_cast<const float2*>(b0_s + 256 + j0);
                    // pair a: row qr; pair b: row qr+8 (fp16x2 activation path)
                    uint32_t ha = hcell2(h2u(acc[mt][0][jt][0] + bi.x, acc[mt][0][jt][1] + bi.y),
                                         h2u(acc[mt][1][jt][0] + bg.x, acc[mt][1][jt][1] + bg.y),
                                         h2u(acc[mt][2][jt][0] + bo.x, acc[mt][2][jt][1] + bo.y));
                    uint32_t hb = hcell2(h2u(acc[mt][0][jt][2] + bi.x, acc[mt][0][jt][3] + bi.y),
                                         h2u(acc[mt][1][jt][2] + bg.x, acc[mt][1][jt][3] + bg.y),
                                         h2u(acc[mt][2][jt][2] + bo.x, acc[mt][2][jt][3] + bo.y));
                    int ra = mg * 32 + mt * 16 + qr;
                    *reinterpret_cast<uint32_t*>(smem + SM_H0 + (ra * HSTR + j0) * 2) = ha;
                    *reinterpret_cast<uint32_t*>(smem + SM_H0 + ((ra + 8) * HSTR + j0) * 2) = hb;
                }
            }
        }
        __syncthreads();       // X fully read, H0 complete

        // ---- prefetch next tile's x into X buffer (overlaps layer1+heads) ----
        if (tn < NTILES) {
            stage_x(sb, tn, tid);
            cp_commit();
        }
        cp_wait<1>();          // first tile: ensures group B (W1+WH); later: no-op
        __syncthreads();

        // ---- layer 1 + h1 as in-register A-frags ----
        uint32_t hfrag[2][2][4];   // [mt][kt-in-quarter][4]
        {
            float acc[2][3][4][4];
#pragma unroll
            for (int mt = 0; mt < 2; mt++)
#pragma unroll
                for (int g = 0; g < 3; g++)
#pragma unroll
                    for (int jt = 0; jt < 4; jt++)
#pragma unroll
                        for (int e = 0; e < 4; e++) acc[mt][g][jt][e] = 0.f;

#pragma unroll 2
            for (int ks = 0; ks < 8; ks++) {
                uint32_t a[2][4];
#pragma unroll
                for (int mt = 0; mt < 2; mt++) {
                    uint32_t addr = sb + SM_H0 +
                        (uint32_t)(((mg * 32 + mt * 16 + rA) * HSTR + ks * 16 + kA) * 2);
                    ldsm4(a[mt][0], a[mt][1], a[mt][2], a[mt][3], addr);
                }
#pragma unroll
                for (int g = 0; g < 3; g++) {
#pragma unroll
                    for (int jp = 0; jp < 2; jp++) {
                        int jb = jqw * 32 + jp * 16;
                        uint32_t addr = sb + SM_W1 +
                            (uint32_t)(((g * 128 + jb + rB) * W1STR + ks * 16 + kB) * 2);
                        uint32_t b0, b1, b2, b3;
                        ldsm4(b0, b1, b2, b3, addr);
#pragma unroll
                        for (int mt = 0; mt < 2; mt++) {
                            mma16816(acc[mt][g][2 * jp],     a[mt], b0, b1);
                            mma16816(acc[mt][g][2 * jp + 1], a[mt], b2, b3);
                        }
                    }
                }
            }
            // epilogue: hcell2 -> packed A-fragments (kt = jp)
#pragma unroll
            for (int mt = 0; mt < 2; mt++) {
#pragma unroll
                for (int jp = 0; jp < 2; jp++) {
#pragma unroll
                    for (int half = 0; half < 2; half++) {
                        int jt = 2 * jp + half;
                        int j0 = jqw * 32 + jt * 8 + qc;
                        float2 bi = *reinterpret_cast<const float2*>(b1_s + j0);
                        float2 bg = *reinterpret_cast<const float2*>(b1_s + 128 + j0);
                        float2 bo = *reinterpret_cast<const float2*>(b1_s + 256 + j0);
                        hfrag[mt][jp][2 * half] =
                            hcell2(h2u(acc[mt][0][jt][0] + bi.x, acc[mt][0][jt][1] + bi.y),
                                   h2u(acc[mt][1][jt][0] + bg.x, acc[mt][1][jt][1] + bg.y),
                                   h2u(acc[mt][2][jt][0] + bo.x, acc[mt][2][jt][1] + bo.y));
                        hfrag[mt][jp][2 * half + 1] =
                            hcell2(h2u(acc[mt][0][jt][2] + bi.x, acc[mt][0][jt][3] + bi.y),
                                   h2u(acc[mt][1][jt][2] + bg.x, acc[mt][1][jt][3] + bg.y),
                                   h2u(acc[mt][2][jt][2] + bo.x, acc[mt][2][jt][3] + bo.y));
                    }
                }
            }
        }

        // ---- heads: partial [m x 17] over this warp's 32-k chunk ----
        float hacc[2][3][4];
#pragma unroll
        for (int mt = 0; mt < 2; mt++)
#pragma unroll
            for (int nt = 0; nt < 3; nt++)
#pragma unroll
                for (int e = 0; e < 4; e++) hacc[mt][nt][e] = 0.f;

#pragma unroll
        for (int kt = 0; kt < 2; kt++) {
            int kg = jqw * 32 + kt * 16;
            uint32_t b0, b1, b2, b3, c0, c1;
            uint32_t addr01 = sb + SM_WH + (uint32_t)(((rB) * WHSTR + kg + kB) * 2);
            ldsm4(b0, b1, b2, b3, addr01);
            uint32_t addr2 = sb + SM_WH +
                (uint32_t)(((16 + (lane & 7)) * WHSTR + kg + ((lane >> 3) & 1) * 8) * 2);
            ldsm2(c0, c1, addr2);
#pragma unroll
            for (int mt = 0; mt < 2; mt++) {
                mma16816(hacc[mt][0], hfrag[mt][kt], b0, b1);
                mma16816(hacc[mt][1], hfrag[mt][kt], b2, b3);
                mma16816(hacc[mt][2], hfrag[mt][kt], c0, c1);
            }
        }

        // ---- 4-way cross-warp (j-quarter) reduction (BUF aliases H0) ----
        __syncthreads();       // all H0 reads done -> alias safe
        float* buf = reinterpret_cast<float*>(smem + SM_BUF);
#pragma unroll
        for (int mt = 0; mt < 2; mt++)
#pragma unroll
            for (int nt = 0; nt < 3; nt++)
#pragma unroll
                for (int e = 0; e < 4; e++) {
                    int n = nt * 8 + qc + (e & 1);
                    if (n < 17) {
                        int m = mg * 32 + mt * 16 + qr + ((e >= 2) ? 8 : 0);
                        buf[(jqw * BM + m) * BUFSTR + n] = hacc[mt][nt][e];
                    }
                }
        __syncthreads();

        if (tid < 2 * BM) {
            int row = tid >> 1, hn = tid & 1;
            float s[8];
#pragma unroll
            for (int c = 0; c < 8; c++) s[c] = bp_s[hn * 8 + c];
#pragma unroll
            for (int q = 0; q < 4; q++) {
                const float* src = buf + (q * BM + row) * BUFSTR + hn * 8;
#pragma unroll
                for (int c = 0; c < 8; c++) s[c] += src[c];
            }
            float4* dst = reinterpret_cast<float4*>(
                out_policy + (size_t)(base + row) * NUM_ACT + hn * 8);
            dst[0] = make_float4(s[0], s[1], s[2], s[3]);
            dst[1] = make_float4(s[4], s[5], s[6], s[7]);
        } else if (tid < 3 * BM) {
            int row = tid - 2 * BM;
            float v = bv_s[0];
#pragma unroll
            for (int q = 0; q < 4; q++) v += buf[(q * BM + row) * BUFSTR + 16];
            out_value[base + row] = v;
        }

        if (tn < NTILES) {
            cp_wait<0>();      // next x tile resident
            __syncthreads();   // visibility of copies + BUF->H0 reuse
        }
    }
}

extern "C" void kernel_launch(void* const* d_in, const int* in_sizes, int n_in,
                              void* d_out, int out_size)
{
    (void)in_sizes; (void)n_in; (void)out_size;
    // 0:x 1:Wih0 2:Whh0(dead) 3:bih0 4:bhh0 5:Wih1 6:Whh1(dead) 7:bih1 8:bhh1
    // 9:Wp 10:bp 11:Wv 12:bv
    const float* x    = (const float*)d_in[0];
    const float* Wih0 = (const float*)d_in[1];
    const float* bih0 = (const float*)d_in[3];
    const float* bhh0 = (const float*)d_in[4];
    const float* Wih1 = (const float*)d_in[5];
    const float* bih1 = (const float*)d_in[7];
    const float* bhh1 = (const float*)d_in[8];
    const float* Wp   = (const float*)d_in[9];
    const float* bp   = (const float*)d_in[10];
    const float* Wv   = (const float*)d_in[11];
    const float* bv   = (const float*)d_in[12];

    float* out        = (float*)d_out;
    float* out_policy = out;
    float* out_value  = out + (size_t)BATCH_N * NUM_ACT;

    prep_weights<<<512, 256>>>(x, Wih0, Wih1, Wp, Wv,
                               bih0, bhh0, bih1, bhh1, bp, bv);

    cudaFuncSetAttribute((const void*)lstm_policy_mma,
                         cudaFuncAttributeMaxDynamicSharedMemorySize, SM_TOTAL);
    lstm_policy_mma<<<NCTA, TPB, SM_TOTAL>>>(out_policy, out_value);
}

// round 14
// speedup vs baseline: 1.3175x; 1.0792x over previous
#include <cuda_runtime.h>
#include <cuda_fp16.h>
#include <cstdint>
#include <math.h>

#define HIDDEN    128
#define INPUT_SZ  64
#define NUM_ACT   16
#define BATCH_N   65536
#define TPB       512
#define NCTA      148
#define FULL_ROWS 56832                // 148*3 tiles of 128 rows
#define TAIL_CTAS 136                  // 136 tiles of 64 rows cover the rest

// padded strides (in halfs) -> conflict-free ldmatrix
#define XSTR   72
#define W0STR  72
#define W1STR  136
#define WHSTR  136
#define HSTR   136
#define BUFSTR 17                      // head reduce buffer stride (floats)

// smem layout (bytes)
#define SM_X    0                      // 128*72*2   = 18432 (live every tile: prefetch target)
#define SM_W0   18432                  // 3*128*72*2 = 55296
#define SM_W1   73728                  // 3*128*136*2= 104448
#define SM_WH   178176                 // 32*136*2   = 8704
#define SM_H0   186880                 // 128*136*2  = 34816
#define SM_BUF  186880                 // [4][<=128][17] f32 (aliases H0, dead at reduce)
#define SM_B0   221696
#define SM_B1   223232
#define SM_BP   224768
#define SM_BV   224832
#define SM_TOTAL 224896

// ---------------- precomputed fp16 tensors / f32 bias sums (device globals) --
__device__ __half gW0h[3 * 128 * 64];     // [g*128+j][64]
__device__ __half gW1h[3 * 128 * 128];    // [g*128+j][128]
__device__ __half gWHh[32 * 128];         // rows 0-15 Wp, 16 Wv, 17-31 zero
__device__ __half gXh[BATCH_N * INPUT_SZ];// x pre-converted to fp16
__device__ float  gB0[384], gB1[384], gBP[16], gBV[1];

__device__ __forceinline__ uint32_t smem_u32(const void* p) {
    uint32_t a;
    asm("{ .reg .u64 t; cvta.to.shared.u64 t, %1; cvt.u32.u64 %0, t; }"
        : "=r"(a) : "l"(p));
    return a;
}
__device__ __forceinline__ void cp16(uint32_t dst, const void* src) {
    asm volatile("cp.async.cg.shared.global [%0], [%1], 16;"
                 :: "r"(dst), "l"(src));
}
__device__ __forceinline__ void cp_commit() {
    asm volatile("cp.async.commit_group;" ::: "memory");
}
template <int N>
__device__ __forceinline__ void cp_wait() {
    asm volatile("cp.async.wait_group %0;" :: "n"(N) : "memory");
}
__device__ __forceinline__ void ldsm4(uint32_t& r0, uint32_t& r1, uint32_t& r2,
                                      uint32_t& r3, uint32_t addr) {
    asm volatile("ldmatrix.sync.aligned.m8n8.x4.shared.b16 {%0,%1,%2,%3}, [%4];"
                 : "=r"(r0), "=r"(r1), "=r"(r2), "=r"(r3) : "r"(addr));
}
__device__ __forceinline__ void ldsm2(uint32_t& r0, uint32_t& r1, uint32_t addr) {
    asm volatile("ldmatrix.sync.aligned.m8n8.x2.shared.b16 {%0,%1}, [%2];"
                 : "=r"(r0), "=r"(r1) : "r"(addr));
}
__device__ __forceinline__ void mma16816(float* d, const uint32_t* a,
                                         uint32_t b0, uint32_t b1) {
    asm volatile(
        "mma.sync.aligned.m16n8k16.row.col.f32.f16.f16.f32 "
        "{%0,%1,%2,%3}, {%4,%5,%6,%7}, {%8,%9}, {%0,%1,%2,%3};"
        : "+f"(d[0]), "+f"(d[1]), "+f"(d[2]), "+f"(d[3])
        : "r"(a[0]), "r"(a[1]), "r"(a[2]), "r"(a[3]), "r"(b0), "r"(b1));
}

// ---------------- fp16x2 activation path ----------------
__device__ __forceinline__ __half2 tanh2(__half2 x) {
    uint32_t xi = *reinterpret_cast<uint32_t*>(&x), yi;
    asm("tanh.approx.f16x2 %0, %1;" : "=r"(yi) : "r"(xi));
    return *reinterpret_cast<__half2*>(&yi);
}
__device__ __forceinline__ uint32_t h2u(float a, float b) {
    __half2 h = __floats2half2_rn(a, b);
    return *reinterpret_cast<uint32_t*>(&h);
}
// packed pair hcell: i,g,o pairs -> h pair (fp16x2)
// sig(x) = 0.5 + 0.5*tanh(x/2);  h = sig(o)*tanh(sig(i)*tanh(g))
__device__ __forceinline__ uint32_t hcell2(uint32_t i2u, uint32_t g2u, uint32_t o2u) {
    const __half2 H = __half2(__half_raw{0x3800}, __half_raw{0x3800});   // (0.5, 0.5)
    __half2 i2 = *reinterpret_cast<__half2*>(&i2u);
    __half2 g2 = *reinterpret_cast<__half2*>(&g2u);
    __half2 o2 = *reinterpret_cast<__half2*>(&o2u);
    __half2 si = __hfma2(tanh2(__hmul2(i2, H)), H, H);
    __half2 tg = tanh2(g2);
    __half2 tc = tanh2(__hmul2(si, tg));
    __half2 so = __hfma2(tanh2(__hmul2(o2, H)), H, H);
    __half2 h  = __hmul2(so, tc);
    return *reinterpret_cast<uint32_t*>(&h);
}
__device__ __forceinline__ int grow_of(int g) {   // live gates i,g,o in 4H blocks
    return (g == 0) ? 0 : (g == 1) ? 2 * HIDDEN : 3 * HIDDEN;
}

// =================== prep kernel: fp32 -> fp16 weights + x, bias sums ========
extern "C" __global__ void prep_weights(const float* __restrict__ x,
                                        const float* __restrict__ Wih0,
                                        const float* __restrict__ Wih1,
                                        const float* __restrict__ Wp,
                                        const float* __restrict__ Wv,
                                        const float* __restrict__ bih0,
                                        const float* __restrict__ bhh0,
                                        const float* __restrict__ bih1,
                                        const float* __restrict__ bhh1,
                                        const float* __restrict__ bp,
                                        const float* __restrict__ bv)
{
    const int tid = blockIdx.x * blockDim.x + threadIdx.x;
    const int nt  = gridDim.x * blockDim.x;
    const int NX8 = BATCH_N * INPUT_SZ / 8;
    for (int idx = tid; idx < NX8; idx += nt) {
        const float4* src = reinterpret_cast<const float4*>(x) + 2 * idx;
        float4 a = __ldg(src), b = __ldg(src + 1);
        uint4 u = make_uint4(h2u(a.x, a.y), h2u(a.z, a.w), h2u(b.x, b.y), h2u(b.z, b.w));
        *(reinterpret_cast<uint4*>(gXh) + idx) = u;
    }
    for (int idx = tid; idx < 3 * 128 * 64; idx += nt) {
        int rr = idx >> 6, c = idx & 63;
        int g = rr >> 7, j = rr & 127;
        gW0h[idx] = __float2half_rn(__ldg(Wih0 + (size_t)(grow_of(g) + j) * 64 + c));
    }
    for (int idx = tid; idx < 3 * 128 * 128; idx += nt) {
        int rr = idx >> 7, c = idx & 127;
        int g = rr >> 7, j = rr & 127;
        gW1h[idx] = __float2half_rn(__ldg(Wih1 + (size_t)(grow_of(g) + j) * 128 + c));
    }
    for (int idx = tid; idx < 32 * 128; idx += nt) {
        int row = idx >> 7, c = idx & 127;
        float v = (row < NUM_ACT) ? __ldg(Wp + row * 128 + c)
                : (row == NUM_ACT) ? __ldg(Wv + c) : 0.0f;
        gWHh[idx] = __float2half_rn(v);
    }
    for (int idx = tid; idx < 384; idx += nt) {
        int g = idx >> 7, j = idx & 127;
        int row = grow_of(g) + j;
        gB0[idx] = __ldg(bih0 + row) + __ldg(bhh0 + row);
        gB1[idx] = __ldg(bih1 + row) + __ldg(bhh1 + row);
    }
    if (tid < NUM_ACT) gBP[tid] = __ldg(bp + tid);
    if (tid == 0) gBV[0] = __ldg(bv);
}

// x rows -> smem via cp.async (8 x 16B chunks per row)
__device__ __forceinline__ void stage_x_n(uint32_t sb, long rowbase, int nrows, int tid) {
    const __half* src0 = gXh + (size_t)rowbase * INPUT_SZ;
    const int nch = nrows * 8;
    for (int id = tid; id < nch; id += TPB) {
        int row = id >> 3, c = id & 7;
        cp16(sb + SM_X + (uint32_t)((row * XSTR + c * 8) * 2),
             src0 + row * INPUT_SZ + c * 8);
    }
}

// =================== tile body: NMT=2 -> 128 rows, NMT=1 -> 64 rows ==========
template <int NMT>
__device__ __forceinline__ void tile_body(char* __restrict__ smem, uint32_t sb,
                                          long base, long next_base, int next_nrows,
                                          const float* __restrict__ b0_s,
                                          const float* __restrict__ b1_s,
                                          const float* __restrict__ bp_s,
                                          const float* __restrict__ bv_s,
                                          float* __restrict__ out_policy,
                                          float* __restrict__ out_value)
{
    const int tid  = threadIdx.x;
    const int lane = tid & 31;
    const int wid  = tid >> 5;
    const int mg   = wid >> 2;         // 0..3 : m-group
    const int jqw  = wid & 3;          // 0..3 : 32-col j-quarter
    const int rA   = lane & 15;
    const int kA   = ((lane >> 4) & 1) * 8;
    const int rB   = (lane & 7) + ((lane >> 4) & 1) * 8;
    const int kB   = ((lane >> 3) & 1) * 8;
    const int qr   = lane >> 2;
    const int qc   = (lane & 3) * 2;
    constexpr int NR = NMT * 64;       // rows in this tile
    const int mrow = mg * (16 * NMT);  // warp's first row

    // ---- layer 0: gates = x @ W0^T -> h0 smem ----
    {
        float acc[NMT][3][4][4];
#pragma unroll
        for (int mt = 0; mt < NMT; mt++)
#pragma unroll
            for (int g = 0; g < 3; g++)
#pragma unroll
                for (int jt = 0; jt < 4; jt++)
#pragma unroll
                    for (int e = 0; e < 4; e++) acc[mt][g][jt][e] = 0.f;

#pragma unroll 2
        for (int ks = 0; ks < 4; ks++) {
            uint32_t a[NMT][4];
#pragma unroll
            for (int mt = 0; mt < NMT; mt++) {
                uint32_t addr = sb + SM_X +
                    (uint32_t)(((mrow + mt * 16 + rA) * XSTR + ks * 16 + kA) * 2);
                ldsm4(a[mt][0], a[mt][1], a[mt][2], a[mt][3], addr);
            }
#pragma unroll
            for (int g = 0; g < 3; g++) {
#pragma unroll
                for (int jp = 0; jp < 2; jp++) {
                    int jb = jqw * 32 + jp * 16;
                    uint32_t addr = sb + SM_W0 +
                        (uint32_t)(((g * 128 + jb + rB) * W0STR + ks * 16 + kB) * 2);
                    uint32_t b0, b1, b2, b3;
                    ldsm4(b0, b1, b2, b3, addr);
#pragma unroll
                    for (int mt = 0; mt < NMT; mt++) {
                        mma16816(acc[mt][g][2 * jp],     a[mt], b0, b1);
                        mma16816(acc[mt][g][2 * jp + 1], a[mt], b2, b3);
                    }
                }
            }
        }
#pragma unroll
        for (int mt = 0; mt < NMT; mt++) {
#pragma unroll
            for (int jt = 0; jt < 4; jt++) {
                int j0 = jqw * 32 + jt * 8 + qc;
                float2 bi = *reinterpret_cast<const float2*>(b0_s + j0);
                float2 bg = *reinterpret_cast<const float2*>(b0_s + 128 + j0);
                float2 bo = *reinterpret_cast<const float2*>(b0_s + 256 + j0);
                uint32_t ha = hcell2(h2u(acc[mt][0][jt][0] + bi.x, acc[mt][0][jt][1] + bi.y),
                                     h2u(acc[mt][1][jt][0] + bg.x, acc[mt][1][jt][1] + bg.y),
                                     h2u(acc[mt][2][jt][0] + bo.x, acc[mt][2][jt][1] + bo.y));
                uint32_t hb = hcell2(h2u(acc[mt][0][jt][2] + bi.x, acc[mt][0][jt][3] + bi.y),
                                     h2u(acc[mt][1][jt][2] + bg.x, acc[mt][1][jt][3] + bg.y),
                                     h2u(acc[mt][2][jt][2] + bo.x, acc[mt][2][jt][3] + bo.y));
                int ra = mrow + mt * 16 + qr;
                *reinterpret_cast<uint32_t*>(smem + SM_H0 + (ra * HSTR + j0) * 2) = ha;
                *reinterpret_cast<uint32_t*>(smem + SM_H0 + ((ra + 8) * HSTR + j0) * 2) = hb;
            }
        }
    }
    __syncthreads();       // X fully read, H0 complete

    // ---- prefetch next tile's x into X buffer (overlaps layer1+heads) ----
    if (next_base >= 0) {
        stage_x_n(sb, next_base, next_nrows, tid);
        cp_commit();
    }
    cp_wait<1>();          // first tile: ensures group B (W1+WH); later: no-op
    __syncthreads();

    // ---- layer 1 + h1 as in-register A-frags ----
    uint32_t hfrag[NMT][2][4];
    {
        float acc[NMT][3][4][4];
#pragma unroll
        for (int mt = 0; mt < NMT; mt++)
#pragma unroll
            for (int g = 0; g < 3; g++)
#pragma unroll
                for (int jt = 0; jt < 4; jt++)
#pragma unroll
                    for (int e = 0; e < 4; e++) acc[mt][g][jt][e] = 0.f;

#pragma unroll 2
        for (int ks = 0; ks < 8; ks++) {
            uint32_t a[NMT][4];
#pragma unroll
            for (int mt = 0; mt < NMT; mt++) {
                uint32_t addr = sb + SM_H0 +
                    (uint32_t)(((mrow + mt * 16 + rA) * HSTR + ks * 16 + kA) * 2);
                ldsm4(a[mt][0], a[mt][1], a[mt][2], a[mt][3], addr);
            }
#pragma unroll
            for (int g = 0; g < 3; g++) {
#pragma unroll
                for (int jp = 0; jp < 2; jp++) {
                    int jb = jqw * 32 + jp * 16;
                    uint32_t addr = sb + SM_W1 +
                        (uint32_t)(((g * 128 + jb + rB) * W1STR + ks * 16 + kB) * 2);
                    uint32_t b0, b1, b2, b3;
                    ldsm4(b0, b1, b2, b3, addr);
#pragma unroll
                    for (int mt = 0; mt < NMT; mt++) {
                        mma16816(acc[mt][g][2 * jp],     a[mt], b0, b1);
                        mma16816(acc[mt][g][2 * jp + 1], a[mt], b2, b3);
                    }
                }
            }
        }
#pragma unroll
        for (int mt = 0; mt < NMT; mt++) {
#pragma unroll
            for (int jp = 0; jp < 2; jp++) {
#pragma unroll
                for (int half = 0; half < 2; half++) {
                    int jt = 2 * jp + half;
                    int j0 = jqw * 32 + jt * 8 + qc;
                    float2 bi = *reinterpret_cast<const float2*>(b1_s + j0);
                    float2 bg = *reinterpret_cast<const float2*>(b1_s + 128 + j0);
                    float2 bo = *reinterpret_cast<const float2*>(b1_s + 256 + j0);
                    hfrag[mt][jp][2 * half] =
                        hcell2(h2u(acc[mt][0][jt][0] + bi.x, acc[mt][0][jt][1] + bi.y),
                               h2u(acc[mt][1][jt][0] + bg.x, acc[mt][1][jt][1] + bg.y),
                               h2u(acc[mt][2][jt][0] + bo.x, acc[mt][2][jt][1] + bo.y));
                    hfrag[mt][jp][2 * half + 1] =
                        hcell2(h2u(acc[mt][0][jt][2] + bi.x, acc[mt][0][jt][3] + bi.y),
                               h2u(acc[mt][1][jt][2] + bg.x, acc[mt][1][jt][3] + bg.y),
                               h2u(acc[mt][2][jt][2] + bo.x, acc[mt][2][jt][3] + bo.y));
                }
            }
        }
    }

    // ---- heads: partial [m x 17] over this warp's 32-k chunk ----
    float hacc[NMT][3][4];
#pragma unroll
    for (int mt = 0; mt < NMT; mt++)
#pragma unroll
        for (int nt = 0; nt < 3; nt++)
#pragma unroll
            for (int e = 0; e < 4; e++) hacc[mt][nt][e] = 0.f;

#pragma unroll
    for (int kt = 0; kt < 2; kt++) {
        int kg = jqw * 32 + kt * 16;
        uint32_t b0, b1, b2, b3, c0, c1;
        uint32_t addr01 = sb + SM_WH + (uint32_t)(((rB) * WHSTR + kg + kB) * 2);
        ldsm4(b0, b1, b2, b3, addr01);
        uint32_t addr2 = sb + SM_WH +
            (uint32_t)(((16 + (lane & 7)) * WHSTR + kg + ((lane >> 3) & 1) * 8) * 2);
        ldsm2(c0, c1, addr2);
#pragma unroll
        for (int mt = 0; mt < NMT; mt++) {
            mma16816(hacc[mt][0], hfrag[mt][kt], b0, b1);
            mma16816(hacc[mt][1], hfrag[mt][kt], b2, b3);
            mma16816(hacc[mt][2], hfrag[mt][kt], c0, c1);
        }
    }

    // ---- 4-way cross-warp (j-quarter) reduction (BUF aliases H0) ----
    __syncthreads();       // all H0 reads done -> alias safe
    float* buf = reinterpret_cast<float*>(smem + SM_BUF);
#pragma unroll
    for (int mt = 0; mt < NMT; mt++)
#pragma unroll
        for (int nt = 0; nt < 3; nt++)
#pragma unroll
            for (int e = 0; e < 4; e++) {
                int n = nt * 8 + qc + (e & 1);
                if (n < 17) {
                    int m = mrow + mt * 16 + qr + ((e >= 2) ? 8 : 0);
                    buf[(jqw * NR + m) * BUFSTR + n] = hacc[mt][nt][e];
                }
            }
    __syncthreads();

    if (tid < 2 * NR) {
        int row = tid >> 1, hn = tid & 1;
        float s[8];
#pragma unroll
        for (int c = 0; c < 8; c++) s[c] = bp_s[hn * 8 + c];
#pragma unroll
        for (int q = 0; q < 4; q++) {
            const float* src = buf + (q * NR + row) * BUFSTR + hn * 8;
#pragma unroll
            for (int c = 0; c < 8; c++) s[c] += src[c];
        }
        float4* dst = reinterpret_cast<float4*>(
            out_policy + (size_t)(base + row) * NUM_ACT + hn * 8);
        dst[0] = make_float4(s[0], s[1], s[2], s[3]);
        dst[1] = make_float4(s[4], s[5], s[6], s[7]);
    } else if (tid < 3 * NR) {
        int row = tid - 2 * NR;
        float v = bv_s[0];
#pragma unroll
        for (int q = 0; q < 4; q++) v += buf[(q * NR + row) * BUFSTR + 16];
        out_value[base + row] = v;
    }

    if (next_base >= 0) {
        cp_wait<0>();      // next x tile resident
        __syncthreads();   // visibility of copies + BUF->H0 reuse
    }
}

// =================== main persistent kernel ==================================
extern "C" __global__ void __launch_bounds__(TPB, 1)
lstm_policy_mma(float* __restrict__ out_policy,
                float* __restrict__ out_value)
{
    extern __shared__ char smem[];
    const uint32_t sb = smem_u32(smem);
    const int tid = threadIdx.x;
    const int b   = blockIdx.x;

    float* b0_s = reinterpret_cast<float*>(smem + SM_B0);
    float* b1_s = reinterpret_cast<float*>(smem + SM_B1);
    float* bp_s = reinterpret_cast<float*>(smem + SM_BP);
    float* bv_s = reinterpret_cast<float*>(smem + SM_BV);

    // ===== prologue: group A = W0 + x(first tile); group B = W1 + WH =====
#pragma unroll
    for (int it = 0; it < 6; it++) {               // W0: 3072 16B chunks
        int id = tid + it * TPB;
        int rr = id >> 3, c = id & 7;
        cp16(sb + SM_W0 + (uint32_t)((rr * W0STR + c * 8) * 2),
             gW0h + rr * 64 + c * 8);
    }
    stage_x_n(sb, (long)b * 128, 128, tid);
    cp_commit();                                   // group A
#pragma unroll
    for (int it = 0; it < 12; it++) {              // W1: 6144 chunks
        int id = tid + it * TPB;
        int rr = id >> 4, c = id & 15;
        cp16(sb + SM_W1 + (uint32_t)((rr * W1STR + c * 8) * 2),
             gW1h + rr * 128 + c * 8);
    }
    {                                              // WH: 512 chunks
        int row = tid >> 4, c = tid & 15;
        cp16(sb + SM_WH + (uint32_t)((row * WHSTR + c * 8) * 2),
             gWHh + row * 128 + c * 8);
    }
    cp_commit();                                   // group B

    if (tid < 384) {
        b0_s[tid] = gB0[tid];
        b1_s[tid] = gB1[tid];
    }
    if (tid < NUM_ACT) bp_s[tid] = gBP[tid];
    if (tid == 0) bv_s[0] = gBV[0];

    cp_wait<1>();          // group A done: W0 + x0 resident
    __syncthreads();

    // ===== schedule: 3 full tiles per CTA, then 136 CTAs take one half tile ==
    const bool tail  = (b < TAIL_CTAS);
    const long base3 = FULL_ROWS + (long)b * 64;
    long bases[3] = { (long)b * 128, (long)(b + NCTA) * 128, (long)(b + 2 * NCTA) * 128 };

#pragma unroll 1
    for (int s = 0; s < 3; s++) {
        long nb;
        int  nn;
        if (s < 2)      { nb = bases[s + 1];          nn = 128; }
        else            { nb = tail ? base3 : -1;     nn = 64;  }
        tile_body<2>(smem, sb, bases[s], nb, nn,
                     b0_s, b1_s, bp_s, bv_s, out_policy, out_value);
    }
    if (tail) {
        tile_body<1>(smem, sb, base3, -1, 0,
                     b0_s, b1_s, bp_s, bv_s, out_policy, out_value);
    }
}

extern "C" void kernel_launch(void* const* d_in, const int* in_sizes, int n_in,
                              void* d_out, int out_size)
{
    (void)in_sizes; (void)n_in; (void)out_size;
    // 0:x 1:Wih0 2:Whh0(dead) 3:bih0 4:bhh0 5:Wih1 6:Whh1(dead) 7:bih1 8:bhh1
    // 9:Wp 10:bp 11:Wv 12:bv
    const float* x    = (const float*)d_in[0];
    const float* Wih0 = (const float*)d_in[1];
    const float* bih0 = (const float*)d_in[3];
    const float* bhh0 = (const float*)d_in[4];
    const float* Wih1 = (const float*)d_in[5];
    const float* bih1 = (const float*)d_in[7];
    const float* bhh1 = (const float*)d_in[8];
    const float* Wp   = (const float*)d_in[9];
    const float* bp   = (const float*)d_in[10];
    const float* Wv   = (const float*)d_in[11];
    const float* bv   = (const float*)d_in[12];

    float* out        = (float*)d_out;
    float* out_policy = out;
    float* out_value  = out + (size_t)BATCH_N * NUM_ACT;

    prep_weights<<<512, 256>>>(x, Wih0, Wih1, Wp, Wv,
                               bih0, bhh0, bih1, bhh1, bp, bv);

    cudaFuncSetAttribute((const void*)lstm_policy_mma,
                         cudaFuncAttributeMaxDynamicSharedMemorySize, SM_TOTAL);
    lstm_policy_mma<<<NCTA, TPB, SM_TOTAL>>>(out_policy, out_value);
}